// round 14
// baseline (speedup 1.0000x reference)
#include <cuda_runtime.h>
#include <math.h>

#define BB   32
#define NN   4096
#define HH   256
#define NNZC 65536
#define PP   16                 // chunks per batch
#define CHUNK (NN / PP)         // 256 rows per block

// ---------------- scratch (no cudaMalloc allowed) ----------------
__device__ int   g_valid[BB * NN];          // 0/1 mask
__device__ float g_scores[BB * NN];         // masked scores (with -inf)
__device__ float g_s2[BB];                  // dot(x[b,0,:], W[H:2H])
__device__ float g_pm[BB * PP];             // per-chunk max
__device__ float g_pz[BB * PP];             // per-chunk sum exp
__device__ float g_pacc[BB * PP * HH];      // per-chunk weighted x sum
__device__ float g_m[BB];                   // global max per batch
__device__ float g_z[BB];                   // global Z per batch

// ---------------- kernels ----------------

__global__ void k_zero() {
    int i = blockIdx.x * blockDim.x + threadIdx.x;
    g_valid[i] = 0;
}

// Scatter valid mask. Detects int64 vs int32 index dtype on device:
// true-int64 batch indices are all < 32; int32 data reinterpreted as
// int64 packs two indices per word and is >= 2^32 with overwhelming
// probability across 8 samples.
__global__ void k_scatter(const void* __restrict__ bp,
                          const void* __restrict__ rp) {
    __shared__ int s_is64;
    if (threadIdx.x == 0) {
        const unsigned long long* b64 = (const unsigned long long*)bp;
        int ok = 1;
        #pragma unroll
        for (int i = 0; i < 8; i++)
            if (b64[i] >= (unsigned long long)BB) ok = 0;
        s_is64 = ok;
    }
    __syncthreads();
    int i = blockIdx.x * blockDim.x + threadIdx.x;
    int bi, ri;
    if (s_is64) {
        bi = (int)((const long long*)bp)[i];
        ri = (int)((const long long*)rp)[i];
    } else {
        bi = ((const int*)bp)[i];
        ri = ((const int*)rp)[i];
    }
    g_valid[bi * NN + ri] = 1;
}

// s2[b] = dot(x[b,0,:], W[H:]). One warp per batch, 32 warps = 1024 threads.
__global__ void k_s2(const float* __restrict__ x, const float* __restrict__ W) {
    int w = threadIdx.x >> 5, lane = threadIdx.x & 31;
    const float* xr = x + (size_t)w * NN * HH;
    float s = 0.f;
    #pragma unroll
    for (int k = 0; k < 8; k++)
        s += xr[lane + k * 32] * W[HH + lane + k * 32];
    #pragma unroll
    for (int o = 16; o > 0; o >>= 1)
        s += __shfl_xor_sync(0xffffffffu, s, o);
    if (lane == 0) g_s2[w] = s;
}

// Main: one block per (chunk p, batch b). Phase 1: per-row score
// (warp-per-row dot, DRAM read). Phase 2: chunk softmax stats +
// exp-weighted accumulation over the same rows (L2 re-read).
__global__ void __launch_bounds__(256)
k_main(const float* __restrict__ x, const float* __restrict__ W,
       const float* __restrict__ bptr) {
    int b = blockIdx.y, p = blockIdx.x;
    int t = threadIdx.x;
    int warp = t >> 5, lane = t & 31;

    __shared__ float sW1[HH];
    __shared__ float sh[CHUNK];
    __shared__ float red[8];
    __shared__ float sm_m;

    sW1[t] = W[t];
    float bias = *bptr;
    float s2   = g_s2[b];
    __syncthreads();

    int row0 = p * CHUNK;
    const float* xb = x + (size_t)b * NN * HH;

    // ---- phase 1: scores (8 warps x 32 rows) ----
    for (int i = 0; i < 32; i++) {
        int r = warp * 32 + i;
        int row = row0 + r;
        const float* xr = xb + (size_t)row * HH;
        float s = 0.f;
        #pragma unroll
        for (int k = 0; k < 8; k++)
            s += xr[lane + k * 32] * sW1[lane + k * 32];
        #pragma unroll
        for (int o = 16; o > 0; o >>= 1)
            s += __shfl_xor_sync(0xffffffffu, s, o);
        if (lane == 0) {
            int v = g_valid[b * NN + row];
            float tot = s + bias + (v ? s2 : 0.f);
            // invalid -> -inf; valid with exact 0 -> -inf (masked_fill(==0))
            float e = (v && tot != 0.f) ? tot : -INFINITY;
            g_scores[b * NN + row] = e;
            sh[r] = e;
        }
    }
    __syncthreads();

    // ---- chunk max ----
    float v = sh[t];
    #pragma unroll
    for (int o = 16; o > 0; o >>= 1)
        v = fmaxf(v, __shfl_xor_sync(0xffffffffu, v, o));
    if (lane == 0) red[warp] = v;
    __syncthreads();
    if (t == 0) {
        float mm = red[0];
        #pragma unroll
        for (int i = 1; i < 8; i++) mm = fmaxf(mm, red[i]);
        sm_m = mm;
    }
    __syncthreads();
    float m = sm_m;

    // ---- weights + chunk Z ----
    float w = (m == -INFINITY) ? 0.f : __expf(sh[t] - m);
    sh[t] = w;  // each thread rewrites only its own slot (read above)
    float zz = w;
    #pragma unroll
    for (int o = 16; o > 0; o >>= 1)
        zz += __shfl_xor_sync(0xffffffffu, zz, o);
    if (lane == 0) red[warp] = zz;
    __syncthreads();
    if (t == 0) {
        float z = 0.f;
        #pragma unroll
        for (int i = 0; i < 8; i++) z += red[i];
        g_pm[b * PP + p] = m;
        g_pz[b * PP + p] = z;
    }

    // ---- phase 2: acc[h] = sum_r w_r * x[b,row0+r,h] (thread t = column h) ----
    const float* xp = xb + (size_t)row0 * HH + t;
    float a0 = 0.f, a1 = 0.f, a2 = 0.f, a3 = 0.f;
    for (int r = 0; r < CHUNK; r += 4) {
        a0 += sh[r + 0] * xp[(size_t)(r + 0) * HH];
        a1 += sh[r + 1] * xp[(size_t)(r + 1) * HH];
        a2 += sh[r + 2] * xp[(size_t)(r + 2) * HH];
        a3 += sh[r + 3] * xp[(size_t)(r + 3) * HH];
    }
    g_pacc[(size_t)(b * PP + p) * HH + t] = (a0 + a1) + (a2 + a3);
}

// Combine partials per batch; write out[b,h]; stash global m, Z.
__global__ void k_combine(float* __restrict__ out) {
    int b = blockIdx.x, t = threadIdx.x;
    __shared__ float sm[PP], sz[PP];
    if (t < PP) { sm[t] = g_pm[b * PP + t]; sz[t] = g_pz[b * PP + t]; }
    __syncthreads();
    float m = -INFINITY;
    #pragma unroll
    for (int p = 0; p < PP; p++) m = fmaxf(m, sm[p]);
    float z = 0.f, o = 0.f;
    #pragma unroll
    for (int p = 0; p < PP; p++) {
        float f = (sm[p] == -INFINITY) ? 0.f : __expf(sm[p] - m);
        z += sz[p] * f;
        o += g_pacc[(size_t)(b * PP + p) * HH + t] * f;
    }
    out[b * HH + t] = o / z;
    if (t == 0) { g_m[b] = m; g_z[b] = z; }
}

// attn[b,n] = exp(score - m_b) / Z_b   (-inf -> 0)
__global__ void k_attn(float* __restrict__ attn) {
    int i = blockIdx.x * blockDim.x + threadIdx.x;
    int b = i >> 12;  // N = 4096
    float s = g_scores[i];
    float a = (s == -INFINITY) ? 0.f : __expf(s - g_m[b]) / g_z[b];
    attn[i] = a;
}

// ---------------- launch ----------------
extern "C" void kernel_launch(void* const* d_in, const int* in_sizes, int n_in,
                              void* d_out, int out_size) {
    const float* x    = (const float*)d_in[0];
    const void*  bi   = d_in[1];              // batch_idx (int64 or int32)
    const void*  ri   = d_in[2];              // row_idx
    const float* W    = (const float*)d_in[3];
    const float* bptr = (const float*)d_in[4];
    float* out = (float*)d_out;

    k_zero   <<<(BB * NN) / 256, 256>>>();
    k_scatter<<<NNZC / 256, 256>>>(bi, ri);
    k_s2     <<<1, 1024>>>(x, W);
    k_main   <<<dim3(PP, BB), 256>>>(x, W, bptr);
    k_combine<<<BB, 256>>>(out);
    if (out_size >= BB * HH + BB * NN)
        k_attn<<<(BB * NN) / 256, 256>>>(out + BB * HH);
}

// round 15
// speedup vs baseline: 1.7828x; 1.7828x over previous
#include <cuda_runtime.h>
#include <math.h>

#define BB    32
#define NN    4096
#define HH    256
#define NNZC  65536
#define PP    32                 // chunks per batch
#define CHUNK (NN / PP)          // 128 rows per block
#define NWARP 16                 // 512 threads

// ---------------- scratch (no cudaMalloc allowed) ----------------
__device__ int   g_valid[BB * NN];
__device__ float g_scores[BB * NN];
__device__ float g_s2[BB];
__device__ float g_pm[BB * PP];
__device__ float g_pz[BB * PP];
__device__ float g_pacc[BB * PP * HH];
__device__ float g_m[BB];
__device__ float g_z[BB];

// ---------------- kernels ----------------

__global__ void k_zero() {
    int i = blockIdx.x * blockDim.x + threadIdx.x;
    g_valid[i] = 0;
}

// Scatter valid mask; detect int64 vs int32 index dtype on device.
__global__ void k_scatter(const void* __restrict__ bp,
                          const void* __restrict__ rp) {
    __shared__ int s_is64;
    if (threadIdx.x == 0) {
        const unsigned long long* b64 = (const unsigned long long*)bp;
        int ok = 1;
        #pragma unroll
        for (int i = 0; i < 8; i++)
            if (b64[i] >= (unsigned long long)BB) ok = 0;
        s_is64 = ok;
    }
    __syncthreads();
    int i = blockIdx.x * blockDim.x + threadIdx.x;
    int bi, ri;
    if (s_is64) {
        bi = (int)((const long long*)bp)[i];
        ri = (int)((const long long*)rp)[i];
    } else {
        bi = ((const int*)bp)[i];
        ri = ((const int*)rp)[i];
    }
    g_valid[bi * NN + ri] = 1;
}

// s2[b] = dot(x[b,0,:], W[H:2H]). One warp per batch.
__global__ void k_s2(const float* __restrict__ x, const float* __restrict__ W) {
    int w = threadIdx.x >> 5, lane = threadIdx.x & 31;
    const float* xr = x + (size_t)w * NN * HH;
    float s = 0.f;
    #pragma unroll
    for (int k = 0; k < 8; k++)
        s += xr[lane + k * 32] * W[HH + lane + k * 32];
    #pragma unroll
    for (int o = 16; o > 0; o >>= 1)
        s += __shfl_xor_sync(0xffffffffu, s, o);
    if (lane == 0) g_s2[w] = s;
}

// Main: single pass over x. One block per (chunk, batch); each warp owns
// 8 rows, holds its row in registers, computes the score, and folds the
// row into a register-resident online-softmax accumulator. x is read once.
__global__ void __launch_bounds__(512, 2)
k_main(const float* __restrict__ x, const float* __restrict__ W,
       const float* __restrict__ bptr) {
    int b = blockIdx.y, p = blockIdx.x;
    int t = threadIdx.x, warp = t >> 5, lane = t & 31;

    __shared__ float s_m[NWARP];
    __shared__ float s_z[NWARP];
    __shared__ float s_acc[NWARP][HH];   // 16 KB

    // W1 held in registers: lane covers cols [lane*4, lane*4+4) and +128
    float4 wa = *(const float4*)(W + lane * 4);
    float4 wc = *(const float4*)(W + 128 + lane * 4);
    float bias = *bptr;
    float s2   = g_s2[b];

    int row0 = p * CHUNK + warp * 8;
    const float* rp = x + ((size_t)b * NN + row0) * HH + lane * 4;

    float m = -INFINITY, z = 0.f;
    float acc[8];
    #pragma unroll
    for (int i = 0; i < 8; i++) acc[i] = 0.f;

    // one-row prefetch to keep loads in flight across the serial chain
    float4 A = *(const float4*)(rp);
    float4 C = *(const float4*)(rp + 128);

    #pragma unroll
    for (int r = 0; r < 8; r++) {
        float4 xa = A, xc = C;
        if (r < 7) {
            A = *(const float4*)(rp + (size_t)(r + 1) * HH);
            C = *(const float4*)(rp + (size_t)(r + 1) * HH + 128);
        }
        // score dot
        float s = xa.x * wa.x + xa.y * wa.y + xa.z * wa.z + xa.w * wa.w
                + xc.x * wc.x + xc.y * wc.y + xc.z * wc.z + xc.w * wc.w;
        #pragma unroll
        for (int o = 16; o > 0; o >>= 1)
            s += __shfl_xor_sync(0xffffffffu, s, o);

        int rowg = row0 + r;
        int v = g_valid[b * NN + rowg];          // broadcast load
        float tot = s + bias + (v ? s2 : 0.f);
        // invalid -> -inf; valid with exact 0 -> -inf (masked_fill(==0))
        float e = (v && tot != 0.f) ? tot : -INFINITY;
        if (lane == 0) g_scores[b * NN + rowg] = e;

        if (e != -INFINITY) {                    // warp-uniform predicate
            if (e > m) {
                float sc = (m == -INFINITY) ? 0.f : __expf(m - e);
                z *= sc;
                #pragma unroll
                for (int i = 0; i < 8; i++) acc[i] *= sc;
                m = e;
            }
            float w = __expf(e - m);
            z += w;
            acc[0] += w * xa.x; acc[1] += w * xa.y;
            acc[2] += w * xa.z; acc[3] += w * xa.w;
            acc[4] += w * xc.x; acc[5] += w * xc.y;
            acc[6] += w * xc.z; acc[7] += w * xc.w;
        }
    }

    // ---- merge 16 warp partials within the block ----
    if (lane == 0) s_m[warp] = m;
    __syncthreads();
    float M = -INFINITY;
    #pragma unroll
    for (int i = 0; i < NWARP; i++) M = fmaxf(M, s_m[i]);

    float sc = (m == -INFINITY) ? 0.f : __expf(m - M);
    #pragma unroll
    for (int i = 0; i < 4; i++) s_acc[warp][lane * 4 + i]       = acc[i]     * sc;
    #pragma unroll
    for (int i = 0; i < 4; i++) s_acc[warp][128 + lane * 4 + i] = acc[4 + i] * sc;
    if (lane == 0) s_z[warp] = z * sc;
    __syncthreads();

    if (t < HH) {
        float a = 0.f;
        #pragma unroll
        for (int w = 0; w < NWARP; w++) a += s_acc[w][t];
        g_pacc[(size_t)(b * PP + p) * HH + t] = a;
    }
    if (t == 0) {
        float Z = 0.f;
        #pragma unroll
        for (int i = 0; i < NWARP; i++) Z += s_z[i];
        g_pm[b * PP + p] = M;
        g_pz[b * PP + p] = Z;
    }
}

// Combine the PP per-chunk partials for each batch; write out[b,h].
__global__ void k_combine(float* __restrict__ out) {
    int b = blockIdx.x, t = threadIdx.x;
    __shared__ float sm[PP], sz[PP];
    if (t < PP) { sm[t] = g_pm[b * PP + t]; sz[t] = g_pz[b * PP + t]; }
    __syncthreads();
    float m = -INFINITY;
    #pragma unroll
    for (int p = 0; p < PP; p++) m = fmaxf(m, sm[p]);
    float z = 0.f, o = 0.f;
    #pragma unroll
    for (int p = 0; p < PP; p++) {
        float f = (sm[p] == -INFINITY) ? 0.f : __expf(sm[p] - m);
        z += sz[p] * f;
        o += g_pacc[(size_t)(b * PP + p) * HH + t] * f;
    }
    out[b * HH + t] = o / z;
    if (t == 0) { g_m[b] = m; g_z[b] = z; }
}

// attn[b,n] = exp(score - m_b) / Z_b   (-inf -> 0)
__global__ void k_attn(float* __restrict__ attn) {
    int i = blockIdx.x * blockDim.x + threadIdx.x;
    int b = i >> 12;  // N = 4096
    float s = g_scores[i];
    attn[i] = (s == -INFINITY) ? 0.f : __expf(s - g_m[b]) / g_z[b];
}

// ---------------- launch ----------------
extern "C" void kernel_launch(void* const* d_in, const int* in_sizes, int n_in,
                              void* d_out, int out_size) {
    const float* x    = (const float*)d_in[0];
    const void*  bi   = d_in[1];
    const void*  ri   = d_in[2];
    const float* W    = (const float*)d_in[3];
    const float* bptr = (const float*)d_in[4];
    float* out = (float*)d_out;

    k_zero   <<<(BB * NN) / 256, 256>>>();
    k_scatter<<<NNZC / 256, 256>>>(bi, ri);
    k_s2     <<<1, 1024>>>(x, W);
    k_main   <<<dim3(PP, BB), 512>>>(x, W, bptr);
    k_combine<<<BB, 256>>>(out);
    if (out_size >= BB * HH + BB * NN)
        k_attn<<<(BB * NN) / 256, 256>>>(out + BB * HH);
}